// round 15
// baseline (speedup 1.0000x reference)
#include <cuda_runtime.h>

// Problem constants (AttCnn): B=16, NF=64, EC=3, H=W=256
#define HW_   65536           // H*W
#define B_    16
#define NF_   64
#define EC_   3
#define NF1_  8
#define NF2_  16
#define QUADS_TOTAL (B_ * HW_ / 4)   // 262144 pixel quads (4 consecutive W pixels)
#define TPB_  128
#define NTILES_ (QUADS_TOTAL / TPB_) // 2048 tiles of 128 quads
#define NCTAS_ 592                   // 148 SMs x 4 resident CTAs

typedef unsigned long long u64;

// Work-stealing ticket (zeroed by reset kernel before each main launch)
__device__ unsigned int g_ticket;

__global__ void reset_ticket_kernel() { g_ticket = 0u; }

__device__ __forceinline__ u64 pk2(float x, float y) {
    u64 r; asm("mov.b64 %0, {%1, %2};" : "=l"(r) : "f"(x), "f"(y)); return r;
}
__device__ __forceinline__ void unpk2(u64 p, float& x, float& y) {
    asm("mov.b64 {%0, %1}, %2;" : "=f"(x), "=f"(y) : "l"(p));
}
// Blackwell packed fp32x2 FMA / ADD (sm_103a). Lanewise bit-identical to
// scalar fma.rn.f32 / add.rn.f32 — preserves the verified numerics exactly.
// NOTE: a packed mul2+add2 PAIR must NEVER be used for the denominator —
// ptxas contracts it to FFMA2 (rounds 5/6/10 all failed at 0.2506236).
__device__ __forceinline__ u64 fma2(u64 a, u64 b, u64 c) {
    u64 d; asm("fma.rn.f32x2 %0, %1, %2, %3;" : "=l"(d) : "l"(a), "l"(b), "l"(c)); return d;
}
__device__ __forceinline__ u64 add2(u64 a, u64 b) {
    u64 d; asm("add.rn.f32x2 %0, %1, %2;" : "=l"(d) : "l"(a), "l"(b)); return d;
}

__device__ __forceinline__ void l2_prefetch(const float* p) {
    asm volatile("prefetch.global.L2 [%0];" :: "l"(p));
}
__device__ __forceinline__ void store_cs(float* p, float4 v) {
    asm volatile("st.global.cs.v4.f32 [%0], {%1, %2, %3, %4};"
                 :: "l"(p), "f"(v.x), "f"(v.y), "f"(v.z), "f"(v.w) : "memory");
}

__device__ __forceinline__ float leaky(float x) {
    return fmaxf(x, 0.0f) + 0.2f * fminf(x, 0.0f);
}

__global__ void __launch_bounds__(TPB_, 4)
attcnn_kernel(const float* __restrict__ fm,   // [B,NF,H,W]
              const float* __restrict__ ex,   // [B,EC,H,W]
              const float* __restrict__ w1,   // [NF1,EC]
              const float* __restrict__ b1,   // [NF1]
              const float* __restrict__ w2,   // [NF2,NF1]
              const float* __restrict__ b2,   // [NF2]
              const float* __restrict__ wm,   // [NF,NF2]
              const float* __restrict__ bm,   // [NF]
              const float* __restrict__ wa,   // [NF,NF2]
              const float* __restrict__ ba,   // [NF]
              float* __restrict__ out)        // [B,NF,H,W]
{
    // ---- shared weights (loaded ONCE per persistent CTA) ----
    __shared__ float s_w1[NF1_ * EC_];
    __shared__ float s_b1[NF1_];
    __shared__ float s_w2[NF2_ * NF1_];
    __shared__ float s_b2[NF2_];
    __shared__ __align__(16) float2 s_wm[NF_ * NF2_];
    __shared__ __align__(16) float2 s_wa[NF_ * NF2_];
    __shared__ __align__(16) float4 s_bma[NF_];         // (bm,bm,ba,ba)
    __shared__ unsigned s_tile;

    const int t = threadIdx.x;
    if (t < NF1_ * EC_)  s_w1[t] = w1[t];
    if (t < NF1_)        s_b1[t] = b1[t];
    for (int i = t; i < NF2_ * NF1_; i += TPB_) s_w2[i] = w2[i];
    if (t < NF2_)        s_b2[t] = b2[t];
    for (int i = t; i < NF_ * NF2_; i += TPB_) {
        float vm = wm[i]; s_wm[i] = make_float2(vm, vm);
        float va = wa[i]; s_wa[i] = make_float2(va, va);
    }
    if (t < NF_) s_bma[t] = make_float4(bm[t], bm[t], ba[t], ba[t]);

    // ---- persistent work-stealing loop over 2048 tiles ----
    for (;;) {
        __syncthreads();                       // also orders first weight fill
        if (t == 0) s_tile = atomicAdd(&g_ticket, 1u);
        __syncthreads();
        const unsigned tile = s_tile;
        if (tile >= NTILES_) break;

        const int quad = (int)tile * TPB_ + t;
        const int b = quad >> 14;              // HW/4 = 16384 quads per plane
        const int q = quad & 16383;

        const size_t chanBase = (size_t)b * (NF_ * HW_) + 4 * (size_t)q;
        const float* fmp = fm + chanBase;
        float*       op  = out + chanBase;

        // ---- warm the fm stream: ring loads ch 0..3, L2 prefetch ch 4..11 ----
        float4 buf[4];
#pragma unroll
        for (int i = 0; i < 4; i++) buf[i] = *(const float4*)(fmp + (size_t)i * HW_);
#pragma unroll
        for (int i = 4; i < 12; i++) l2_prefetch(fmp + (size_t)i * HW_);

        // ---- front-end MLP for the 4 pixels of this quad ----
        // Verified per-dot semantics: acc=0; ascending c: acc=fma(w[c],x[c],acc);
        // then +bias (separate rn add); then leaky.
        const size_t exBase = (size_t)b * (EC_ * HW_) + 4 * (size_t)q;
        const float4 e0 = *(const float4*)(ex + exBase);
        const float4 e1 = *(const float4*)(ex + exBase + HW_);
        const float4 e2 = *(const float4*)(ex + exBase + 2 * HW_);

        float f10[NF1_], f11[NF1_], f12[NF1_], f13[NF1_];
#pragma unroll
        for (int i = 0; i < NF1_; i++) {
            float w0 = s_w1[i * 3], wv1 = s_w1[i * 3 + 1], wv2 = s_w1[i * 3 + 2];
            float bb = s_b1[i];
            float s0 = fmaf(wv2, e2.x, fmaf(wv1, e1.x, fmaf(w0, e0.x, 0.0f)));
            float s1 = fmaf(wv2, e2.y, fmaf(wv1, e1.y, fmaf(w0, e0.y, 0.0f)));
            float s2 = fmaf(wv2, e2.z, fmaf(wv1, e1.z, fmaf(w0, e0.z, 0.0f)));
            float s3 = fmaf(wv2, e2.w, fmaf(wv1, e1.w, fmaf(w0, e0.w, 0.0f)));
            f10[i] = leaky(__fadd_rn(s0, bb));
            f11[i] = leaky(__fadd_rn(s1, bb));
            f12[i] = leaky(__fadd_rn(s2, bb));
            f13[i] = leaky(__fadd_rn(s3, bb));
        }

        u64 f2lo[NF2_], f2hi[NF2_];   // fea2 packed: lo=(px0,px1), hi=(px2,px3)
#pragma unroll
        for (int i = 0; i < NF2_; i++) {
            float s0 = 0.0f, s1 = 0.0f, s2 = 0.0f, s3 = 0.0f;
#pragma unroll
            for (int j = 0; j < NF1_; j++) {   // sequential ascending j — do not split
                float w = s_w2[i * NF1_ + j];
                s0 = fmaf(w, f10[j], s0);
                s1 = fmaf(w, f11[j], s1);
                s2 = fmaf(w, f12[j], s2);
                s3 = fmaf(w, f13[j], s3);
            }
            float bb = s_b2[i];
            f2lo[i] = pk2(leaky(__fadd_rn(s0, bb)), leaky(__fadd_rn(s1, bb)));
            f2hi[i] = pk2(leaky(__fadd_rn(s2, bb)), leaky(__fadd_rn(s3, bb)));
        }

        // ---- main 64-channel loop: 4-deep LDG ring + L2 prefetch @+12 ----
#pragma unroll 4
        for (int o = 0; o < NF_; o++) {
            const float4 fv = buf[o & 3];
            if (o < NF_ - 4)
                buf[o & 3] = *(const float4*)(fmp + (size_t)(o + 4) * HW_);
            if (o + 12 < NF_)
                l2_prefetch(fmp + (size_t)(o + 12) * HW_);

            const ulonglong2* wmq = (const ulonglong2*)&s_wm[o * NF2_];
            const ulonglong2* waq = (const ulonglong2*)&s_wa[o * NF2_];
            const ulonglong2  bq  = *(const ulonglong2*)&s_bma[o];

            // 4 independent sequential chains (m/a × lo/hi) — order preserved
            u64 mlo = 0ull, mhi = 0ull, alo = 0ull, ahi = 0ull;
#pragma unroll
            for (int j = 0; j < NF2_ / 2; j++) {
                ulonglong2 wmv = wmq[j];
                ulonglong2 wav = waq[j];
                mlo = fma2(wmv.x, f2lo[2 * j],     mlo);
                mlo = fma2(wmv.y, f2lo[2 * j + 1], mlo);
                mhi = fma2(wmv.x, f2hi[2 * j],     mhi);
                mhi = fma2(wmv.y, f2hi[2 * j + 1], mhi);
                alo = fma2(wav.x, f2lo[2 * j],     alo);
                alo = fma2(wav.y, f2lo[2 * j + 1], alo);
                ahi = fma2(wav.x, f2hi[2 * j],     ahi);
                ahi = fma2(wav.y, f2hi[2 * j + 1], ahi);
            }
            mlo = add2(mlo, bq.x);  mhi = add2(mhi, bq.x);   // bias after dot
            alo = add2(alo, bq.y);  ahi = add2(ahi, bq.y);

            float m0, m1, m2, m3, a0, a1, a2, a3;
            unpk2(mlo, m0, m1); unpk2(mhi, m2, m3);
            unpk2(alo, a0, a1); unpk2(ahi, a2, a3);

            // denom = 1 + fm*mul — SCALAR rn intrinsics only (contraction-proof)
            float d0 = __fadd_rn(1.0f, __fmul_rn(fv.x, m0));
            float d1 = __fadd_rn(1.0f, __fmul_rn(fv.y, m1));
            float d2 = __fadd_rn(1.0f, __fmul_rn(fv.z, m2));
            float d3 = __fadd_rn(1.0f, __fmul_rn(fv.w, m3));

            float4 ov;
            ov.x = __fdividef(a0, d0);
            ov.y = __fdividef(a1, d1);
            ov.z = __fdividef(a2, d2);
            ov.w = __fdividef(a3, d3);

            // streaming store (evict-first)
            store_cs(op + (size_t)o * HW_, ov);
        }
    }
}

extern "C" void kernel_launch(void* const* d_in, const int* in_sizes, int n_in,
                              void* d_out, int out_size)
{
    const float* fm = (const float*)d_in[0];
    const float* ex = (const float*)d_in[1];
    const float* w1 = (const float*)d_in[2];
    const float* b1 = (const float*)d_in[3];
    const float* w2 = (const float*)d_in[4];
    const float* b2 = (const float*)d_in[5];
    const float* wm = (const float*)d_in[6];
    const float* bm = (const float*)d_in[7];
    const float* wa = (const float*)d_in[8];
    const float* ba = (const float*)d_in[9];
    float* out = (float*)d_out;

    reset_ticket_kernel<<<1, 1>>>();   // same stream: ordered before main kernel
    attcnn_kernel<<<NCTAS_, TPB_>>>(fm, ex, w1, b1, w2, b2, wm, bm, wa, ba, out);
}

// round 16
// speedup vs baseline: 1.0969x; 1.0969x over previous
#include <cuda_runtime.h>

// Problem constants (AttCnn): B=16, NF=64, EC=3, H=W=256
#define HW_   65536           // H*W
#define B_    16
#define NF_   64
#define EC_   3
#define NF1_  8
#define NF2_  16
#define QUADS_TOTAL (B_ * HW_ / 4)   // 262144 pixel quads (4 consecutive W pixels)
#define TPB_  128
#define PFD_  20                     // L2 prefetch distance (r7 used 12; lead was marginal)

typedef unsigned long long u64;

__device__ __forceinline__ u64 pk2(float x, float y) {
    u64 r; asm("mov.b64 %0, {%1, %2};" : "=l"(r) : "f"(x), "f"(y)); return r;
}
__device__ __forceinline__ void unpk2(u64 p, float& x, float& y) {
    asm("mov.b64 {%0, %1}, %2;" : "=f"(x), "=f"(y) : "l"(p));
}
// Blackwell packed fp32x2 FMA / ADD (sm_103a). Lanewise bit-identical to
// scalar fma.rn.f32 / add.rn.f32 — preserves the verified numerics exactly.
// NOTE: a packed mul2+add2 PAIR must NEVER be used for the denominator —
// ptxas contracts it to FFMA2 (rounds 5/6/10 all failed at 0.2506236).
__device__ __forceinline__ u64 fma2(u64 a, u64 b, u64 c) {
    u64 d; asm("fma.rn.f32x2 %0, %1, %2, %3;" : "=l"(d) : "l"(a), "l"(b), "l"(c)); return d;
}
__device__ __forceinline__ u64 add2(u64 a, u64 b) {
    u64 d; asm("add.rn.f32x2 %0, %1, %2;" : "=l"(d) : "l"(a), "l"(b)); return d;
}

__device__ __forceinline__ void l2_prefetch(const float* p) {
    asm volatile("prefetch.global.L2 [%0];" :: "l"(p));
}
__device__ __forceinline__ void store_cs(float* p, float4 v) {
    asm volatile("st.global.cs.v4.f32 [%0], {%1, %2, %3, %4};"
                 :: "l"(p), "f"(v.x), "f"(v.y), "f"(v.z), "f"(v.w) : "memory");
}

__device__ __forceinline__ float leaky(float x) {
    return fmaxf(x, 0.0f) + 0.2f * fminf(x, 0.0f);
}

__global__ void __launch_bounds__(TPB_, 4)
attcnn_kernel(const float* __restrict__ fm,   // [B,NF,H,W]
              const float* __restrict__ ex,   // [B,EC,H,W]
              const float* __restrict__ w1,   // [NF1,EC]
              const float* __restrict__ b1,   // [NF1]
              const float* __restrict__ w2,   // [NF2,NF1]
              const float* __restrict__ b2,   // [NF2]
              const float* __restrict__ wm,   // [NF,NF2]
              const float* __restrict__ bm,   // [NF]
              const float* __restrict__ wa,   // [NF,NF2]
              const float* __restrict__ ba,   // [NF]
              float* __restrict__ out)        // [B,NF,H,W]
{
    // ---- shared weights (full fp32, heads duplicated (w,w) for packed lanes) ----
    __shared__ float s_w1[NF1_ * EC_];
    __shared__ float s_b1[NF1_];
    __shared__ float s_w2[NF2_ * NF1_];
    __shared__ float s_b2[NF2_];
    __shared__ __align__(16) float2 s_wm[NF_ * NF2_];
    __shared__ __align__(16) float2 s_wa[NF_ * NF2_];
    __shared__ __align__(16) float4 s_bma[NF_];         // (bm,bm,ba,ba)

    const int t = threadIdx.x;
    if (t < NF1_ * EC_)  s_w1[t] = w1[t];
    if (t < NF1_)        s_b1[t] = b1[t];
    for (int i = t; i < NF2_ * NF1_; i += TPB_) s_w2[i] = w2[i];
    if (t < NF2_)        s_b2[t] = b2[t];
    for (int i = t; i < NF_ * NF2_; i += TPB_) {
        float vm = wm[i]; s_wm[i] = make_float2(vm, vm);
        float va = wa[i]; s_wa[i] = make_float2(va, va);
    }
    if (t < NF_) s_bma[t] = make_float4(bm[t], bm[t], ba[t], ba[t]);
    __syncthreads();

    const int quad = blockIdx.x * TPB_ + t;   // grid exactly covers QUADS_TOTAL
    const int b = quad >> 14;                 // HW/4 = 16384 quads per plane
    const int q = quad & 16383;

    const size_t chanBase = (size_t)b * (NF_ * HW_) + 4 * (size_t)q;
    const float* fmp = fm + chanBase;
    float*       op  = out + chanBase;

    // ---- warm the fm stream: ring loads for ch 0..3, L2 prefetch for 4..PFD-1 ----
    float4 buf[4];
#pragma unroll
    for (int i = 0; i < 4; i++) buf[i] = *(const float4*)(fmp + (size_t)i * HW_);
#pragma unroll
    for (int i = 4; i < PFD_; i++) l2_prefetch(fmp + (size_t)i * HW_);

    // ---- front-end MLP for the 4 pixels of this quad ----
    // Verified per-dot semantics: acc=0; ascending c: acc=fma(w[c],x[c],acc);
    // then +bias (separate rn add); then leaky.
    const size_t exBase = (size_t)b * (EC_ * HW_) + 4 * (size_t)q;
    const float4 e0 = *(const float4*)(ex + exBase);
    const float4 e1 = *(const float4*)(ex + exBase + HW_);
    const float4 e2 = *(const float4*)(ex + exBase + 2 * HW_);

    float f10[NF1_], f11[NF1_], f12[NF1_], f13[NF1_];
#pragma unroll
    for (int i = 0; i < NF1_; i++) {
        float w0 = s_w1[i * 3], wv1 = s_w1[i * 3 + 1], wv2 = s_w1[i * 3 + 2];
        float bb = s_b1[i];
        float s0 = fmaf(wv2, e2.x, fmaf(wv1, e1.x, fmaf(w0, e0.x, 0.0f)));
        float s1 = fmaf(wv2, e2.y, fmaf(wv1, e1.y, fmaf(w0, e0.y, 0.0f)));
        float s2 = fmaf(wv2, e2.z, fmaf(wv1, e1.z, fmaf(w0, e0.z, 0.0f)));
        float s3 = fmaf(wv2, e2.w, fmaf(wv1, e1.w, fmaf(w0, e0.w, 0.0f)));
        f10[i] = leaky(__fadd_rn(s0, bb));
        f11[i] = leaky(__fadd_rn(s1, bb));
        f12[i] = leaky(__fadd_rn(s2, bb));
        f13[i] = leaky(__fadd_rn(s3, bb));
    }

    u64 f2lo[NF2_], f2hi[NF2_];   // fea2 packed: lo=(px0,px1), hi=(px2,px3)
#pragma unroll
    for (int i = 0; i < NF2_; i++) {
        float s0 = 0.0f, s1 = 0.0f, s2 = 0.0f, s3 = 0.0f;
#pragma unroll
        for (int j = 0; j < NF1_; j++) {   // sequential ascending j — do not split
            float w = s_w2[i * NF1_ + j];
            s0 = fmaf(w, f10[j], s0);
            s1 = fmaf(w, f11[j], s1);
            s2 = fmaf(w, f12[j], s2);
            s3 = fmaf(w, f13[j], s3);
        }
        float bb = s_b2[i];
        f2lo[i] = pk2(leaky(__fadd_rn(s0, bb)), leaky(__fadd_rn(s1, bb)));
        f2hi[i] = pk2(leaky(__fadd_rn(s2, bb)), leaky(__fadd_rn(s3, bb)));
    }

    // ---- main 64-channel loop: 4-deep LDG ring + L2 prefetch at distance PFD ----
#pragma unroll 4
    for (int o = 0; o < NF_; o++) {
        const float4 fv = buf[o & 3];
        if (o < NF_ - 4)
            buf[o & 3] = *(const float4*)(fmp + (size_t)(o + 4) * HW_);
        if (o + PFD_ < NF_)
            l2_prefetch(fmp + (size_t)(o + PFD_) * HW_);

        const ulonglong2* wmq = (const ulonglong2*)&s_wm[o * NF2_];
        const ulonglong2* waq = (const ulonglong2*)&s_wa[o * NF2_];
        const ulonglong2  bq  = *(const ulonglong2*)&s_bma[o];

        // 4 independent sequential chains (m/a × lo/hi) — order per chain preserved
        u64 mlo = 0ull, mhi = 0ull, alo = 0ull, ahi = 0ull;
#pragma unroll
        for (int j = 0; j < NF2_ / 2; j++) {
            ulonglong2 wmv = wmq[j];
            ulonglong2 wav = waq[j];
            mlo = fma2(wmv.x, f2lo[2 * j],     mlo);
            mlo = fma2(wmv.y, f2lo[2 * j + 1], mlo);
            mhi = fma2(wmv.x, f2hi[2 * j],     mhi);
            mhi = fma2(wmv.y, f2hi[2 * j + 1], mhi);
            alo = fma2(wav.x, f2lo[2 * j],     alo);
            alo = fma2(wav.y, f2lo[2 * j + 1], alo);
            ahi = fma2(wav.x, f2hi[2 * j],     ahi);
            ahi = fma2(wav.y, f2hi[2 * j + 1], ahi);
        }
        mlo = add2(mlo, bq.x);  mhi = add2(mhi, bq.x);   // bias after dot
        alo = add2(alo, bq.y);  ahi = add2(ahi, bq.y);

        float m0, m1, m2, m3, a0, a1, a2, a3;
        unpk2(mlo, m0, m1); unpk2(mhi, m2, m3);
        unpk2(alo, a0, a1); unpk2(ahi, a2, a3);

        // denom = 1 + fm*mul — SCALAR rn intrinsics only (contraction-proof)
        float d0 = __fadd_rn(1.0f, __fmul_rn(fv.x, m0));
        float d1 = __fadd_rn(1.0f, __fmul_rn(fv.y, m1));
        float d2 = __fadd_rn(1.0f, __fmul_rn(fv.z, m2));
        float d3 = __fadd_rn(1.0f, __fmul_rn(fv.w, m3));

        float4 ov;
        ov.x = __fdividef(a0, d0);
        ov.y = __fdividef(a1, d1);
        ov.z = __fdividef(a2, d2);
        ov.w = __fdividef(a3, d3);

        // streaming store (evict-first) — keeps prefetched fm lines resident in L2
        store_cs(op + (size_t)o * HW_, ov);
    }
}

extern "C" void kernel_launch(void* const* d_in, const int* in_sizes, int n_in,
                              void* d_out, int out_size)
{
    const float* fm = (const float*)d_in[0];
    const float* ex = (const float*)d_in[1];
    const float* w1 = (const float*)d_in[2];
    const float* b1 = (const float*)d_in[3];
    const float* w2 = (const float*)d_in[4];
    const float* b2 = (const float*)d_in[5];
    const float* wm = (const float*)d_in[6];
    const float* bm = (const float*)d_in[7];
    const float* wa = (const float*)d_in[8];
    const float* ba = (const float*)d_in[9];
    float* out = (float*)d_out;

    const int blocks = QUADS_TOTAL / TPB_;   // 2048, exact cover
    attcnn_kernel<<<blocks, TPB_>>>(fm, ex, w1, b1, w2, b2, wm, bm, wa, ba, out);
}

// round 17
// speedup vs baseline: 1.1020x; 1.0047x over previous
#include <cuda_runtime.h>

// Problem constants (AttCnn): B=16, NF=64, EC=3, H=W=256
#define HW_   65536           // H*W
#define B_    16
#define NF_   64
#define EC_   3
#define NF1_  8
#define NF2_  16
#define QUADS_TOTAL (B_ * HW_ / 4)   // 262144 pixel quads (4 consecutive W pixels)
#define TPB_  256                    // 2 CTAs/SM x 8 warps = same 16 warps/SM, half the blocks
#define PFD_  12                     // L2 prefetch distance (12 vs 20 measured equivalent)

typedef unsigned long long u64;

__device__ __forceinline__ u64 pk2(float x, float y) {
    u64 r; asm("mov.b64 %0, {%1, %2};" : "=l"(r) : "f"(x), "f"(y)); return r;
}
__device__ __forceinline__ void unpk2(u64 p, float& x, float& y) {
    asm("mov.b64 {%0, %1}, %2;" : "=f"(x), "=f"(y) : "l"(p));
}
// Blackwell packed fp32x2 FMA / ADD (sm_103a). Lanewise bit-identical to
// scalar fma.rn.f32 / add.rn.f32 — preserves the verified numerics exactly.
// NOTE: a packed mul2+add2 PAIR must NEVER be used for the denominator —
// ptxas contracts it to FFMA2 (rounds 5/6/10 all failed at 0.2506236).
__device__ __forceinline__ u64 fma2(u64 a, u64 b, u64 c) {
    u64 d; asm("fma.rn.f32x2 %0, %1, %2, %3;" : "=l"(d) : "l"(a), "l"(b), "l"(c)); return d;
}
__device__ __forceinline__ u64 add2(u64 a, u64 b) {
    u64 d; asm("add.rn.f32x2 %0, %1, %2;" : "=l"(d) : "l"(a), "l"(b)); return d;
}

__device__ __forceinline__ void l2_prefetch(const float* p) {
    asm volatile("prefetch.global.L2 [%0];" :: "l"(p));
}
__device__ __forceinline__ void store_cs(float* p, float4 v) {
    asm volatile("st.global.cs.v4.f32 [%0], {%1, %2, %3, %4};"
                 :: "l"(p), "f"(v.x), "f"(v.y), "f"(v.z), "f"(v.w) : "memory");
}

__device__ __forceinline__ float leaky(float x) {
    return fmaxf(x, 0.0f) + 0.2f * fminf(x, 0.0f);
}

__global__ void __launch_bounds__(TPB_, 2)
attcnn_kernel(const float* __restrict__ fm,   // [B,NF,H,W]
              const float* __restrict__ ex,   // [B,EC,H,W]
              const float* __restrict__ w1,   // [NF1,EC]
              const float* __restrict__ b1,   // [NF1]
              const float* __restrict__ w2,   // [NF2,NF1]
              const float* __restrict__ b2,   // [NF2]
              const float* __restrict__ wm,   // [NF,NF2]
              const float* __restrict__ bm,   // [NF]
              const float* __restrict__ wa,   // [NF,NF2]
              const float* __restrict__ ba,   // [NF]
              float* __restrict__ out)        // [B,NF,H,W]
{
    // ---- shared weights (full fp32, heads duplicated (w,w) for packed lanes) ----
    __shared__ float s_w1[NF1_ * EC_];
    __shared__ float s_b1[NF1_];
    __shared__ float s_w2[NF2_ * NF1_];
    __shared__ float s_b2[NF2_];
    __shared__ __align__(16) float2 s_wm[NF_ * NF2_];
    __shared__ __align__(16) float2 s_wa[NF_ * NF2_];
    __shared__ __align__(16) float4 s_bma[NF_];         // (bm,bm,ba,ba)

    const int t = threadIdx.x;
    if (t < NF1_ * EC_)  s_w1[t] = w1[t];
    if (t < NF1_)        s_b1[t] = b1[t];
    for (int i = t; i < NF2_ * NF1_; i += TPB_) s_w2[i] = w2[i];
    if (t < NF2_)        s_b2[t] = b2[t];
    for (int i = t; i < NF_ * NF2_; i += TPB_) {
        float vm = wm[i]; s_wm[i] = make_float2(vm, vm);
        float va = wa[i]; s_wa[i] = make_float2(va, va);
    }
    if (t < NF_) s_bma[t] = make_float4(bm[t], bm[t], ba[t], ba[t]);
    __syncthreads();

    const int quad = blockIdx.x * TPB_ + t;   // grid exactly covers QUADS_TOTAL
    const int b = quad >> 14;                 // HW/4 = 16384 quads per plane
    const int q = quad & 16383;

    const size_t chanBase = (size_t)b * (NF_ * HW_) + 4 * (size_t)q;
    const float* fmp = fm + chanBase;
    float*       op  = out + chanBase;

    // ---- warm the fm stream: ring loads for ch 0..3, L2 prefetch for 4..PFD-1 ----
    float4 buf[4];
#pragma unroll
    for (int i = 0; i < 4; i++) buf[i] = *(const float4*)(fmp + (size_t)i * HW_);
#pragma unroll
    for (int i = 4; i < PFD_; i++) l2_prefetch(fmp + (size_t)i * HW_);

    // ---- front-end MLP for the 4 pixels of this quad ----
    // Verified per-dot semantics: acc=0; ascending c: acc=fma(w[c],x[c],acc);
    // then +bias (separate rn add); then leaky.
    const size_t exBase = (size_t)b * (EC_ * HW_) + 4 * (size_t)q;
    const float4 e0 = *(const float4*)(ex + exBase);
    const float4 e1 = *(const float4*)(ex + exBase + HW_);
    const float4 e2 = *(const float4*)(ex + exBase + 2 * HW_);

    float f10[NF1_], f11[NF1_], f12[NF1_], f13[NF1_];
#pragma unroll
    for (int i = 0; i < NF1_; i++) {
        float w0 = s_w1[i * 3], wv1 = s_w1[i * 3 + 1], wv2 = s_w1[i * 3 + 2];
        float bb = s_b1[i];
        float s0 = fmaf(wv2, e2.x, fmaf(wv1, e1.x, fmaf(w0, e0.x, 0.0f)));
        float s1 = fmaf(wv2, e2.y, fmaf(wv1, e1.y, fmaf(w0, e0.y, 0.0f)));
        float s2 = fmaf(wv2, e2.z, fmaf(wv1, e1.z, fmaf(w0, e0.z, 0.0f)));
        float s3 = fmaf(wv2, e2.w, fmaf(wv1, e1.w, fmaf(w0, e0.w, 0.0f)));
        f10[i] = leaky(__fadd_rn(s0, bb));
        f11[i] = leaky(__fadd_rn(s1, bb));
        f12[i] = leaky(__fadd_rn(s2, bb));
        f13[i] = leaky(__fadd_rn(s3, bb));
    }

    u64 f2lo[NF2_], f2hi[NF2_];   // fea2 packed: lo=(px0,px1), hi=(px2,px3)
#pragma unroll
    for (int i = 0; i < NF2_; i++) {
        float s0 = 0.0f, s1 = 0.0f, s2 = 0.0f, s3 = 0.0f;
#pragma unroll
        for (int j = 0; j < NF1_; j++) {   // sequential ascending j — do not split
            float w = s_w2[i * NF1_ + j];
            s0 = fmaf(w, f10[j], s0);
            s1 = fmaf(w, f11[j], s1);
            s2 = fmaf(w, f12[j], s2);
            s3 = fmaf(w, f13[j], s3);
        }
        float bb = s_b2[i];
        f2lo[i] = pk2(leaky(__fadd_rn(s0, bb)), leaky(__fadd_rn(s1, bb)));
        f2hi[i] = pk2(leaky(__fadd_rn(s2, bb)), leaky(__fadd_rn(s3, bb)));
    }

    // ---- main 64-channel loop: 4-deep LDG ring + L2 prefetch at distance PFD ----
#pragma unroll 4
    for (int o = 0; o < NF_; o++) {
        const float4 fv = buf[o & 3];
        if (o < NF_ - 4)
            buf[o & 3] = *(const float4*)(fmp + (size_t)(o + 4) * HW_);
        if (o + PFD_ < NF_)
            l2_prefetch(fmp + (size_t)(o + PFD_) * HW_);

        const ulonglong2* wmq = (const ulonglong2*)&s_wm[o * NF2_];
        const ulonglong2* waq = (const ulonglong2*)&s_wa[o * NF2_];
        const ulonglong2  bq  = *(const ulonglong2*)&s_bma[o];

        // 4 independent sequential chains (m/a × lo/hi) — order per chain preserved
        u64 mlo = 0ull, mhi = 0ull, alo = 0ull, ahi = 0ull;
#pragma unroll
        for (int j = 0; j < NF2_ / 2; j++) {
            ulonglong2 wmv = wmq[j];
            ulonglong2 wav = waq[j];
            mlo = fma2(wmv.x, f2lo[2 * j],     mlo);
            mlo = fma2(wmv.y, f2lo[2 * j + 1], mlo);
            mhi = fma2(wmv.x, f2hi[2 * j],     mhi);
            mhi = fma2(wmv.y, f2hi[2 * j + 1], mhi);
            alo = fma2(wav.x, f2lo[2 * j],     alo);
            alo = fma2(wav.y, f2lo[2 * j + 1], alo);
            ahi = fma2(wav.x, f2hi[2 * j],     ahi);
            ahi = fma2(wav.y, f2hi[2 * j + 1], ahi);
        }
        mlo = add2(mlo, bq.x);  mhi = add2(mhi, bq.x);   // bias after dot
        alo = add2(alo, bq.y);  ahi = add2(ahi, bq.y);

        float m0, m1, m2, m3, a0, a1, a2, a3;
        unpk2(mlo, m0, m1); unpk2(mhi, m2, m3);
        unpk2(alo, a0, a1); unpk2(ahi, a2, a3);

        // denom = 1 + fm*mul — SCALAR rn intrinsics only (contraction-proof)
        float d0 = __fadd_rn(1.0f, __fmul_rn(fv.x, m0));
        float d1 = __fadd_rn(1.0f, __fmul_rn(fv.y, m1));
        float d2 = __fadd_rn(1.0f, __fmul_rn(fv.z, m2));
        float d3 = __fadd_rn(1.0f, __fmul_rn(fv.w, m3));

        float4 ov;
        ov.x = __fdividef(a0, d0);
        ov.y = __fdividef(a1, d1);
        ov.z = __fdividef(a2, d2);
        ov.w = __fdividef(a3, d3);

        // streaming store (evict-first) — keeps prefetched fm lines resident in L2
        store_cs(op + (size_t)o * HW_, ov);
    }
}

extern "C" void kernel_launch(void* const* d_in, const int* in_sizes, int n_in,
                              void* d_out, int out_size)
{
    const float* fm = (const float*)d_in[0];
    const float* ex = (const float*)d_in[1];
    const float* w1 = (const float*)d_in[2];
    const float* b1 = (const float*)d_in[3];
    const float* w2 = (const float*)d_in[4];
    const float* b2 = (const float*)d_in[5];
    const float* wm = (const float*)d_in[6];
    const float* bm = (const float*)d_in[7];
    const float* wa = (const float*)d_in[8];
    const float* ba = (const float*)d_in[9];
    float* out = (float*)d_out;

    const int blocks = QUADS_TOTAL / TPB_;   // 1024, exact cover
    attcnn_kernel<<<blocks, TPB_>>>(fm, ex, w1, b1, w2, b2, wm, bm, wa, ba, out);
}